// round 1
// baseline (speedup 1.0000x reference)
#include <cuda_runtime.h>

// TempoStateRNNCell: c_t = a_t * c_{t-1} + b_t along time axis.
// inputs: (16, 2048, 4096) fp32 where [:, :, :2048] = a, [:, :, 2048:] = b
// output: (16, 2048, 2048) fp32
//
// One thread per (batch, unit) sequence. At a fixed timestep the 2048
// threads of a batch touch contiguous rows of a, b, c -> fully coalesced.
// Loads for step t+1 are independent of the serial carry, so unrolling
// exposes MLP and the kernel rides the HBM roofline (~768 MB traffic).

#ifndef TSC_UNITS
#define TSC_UNITS 2048
#endif
#define TSC_T 2048
#define TSC_BATCH 16
#define TSC_ROW (2 * TSC_UNITS)   // 4096 floats per (batch, t) input row

__global__ void __launch_bounds__(256, 8)
tempo_scan_kernel(const float* __restrict__ in, float* __restrict__ out)
{
    const int gid = blockIdx.x * blockDim.x + threadIdx.x;   // 0 .. 32767
    const int batch = gid >> 11;          // / 2048
    const int unit  = gid & (TSC_UNITS - 1);

    // Base pointers for this sequence
    const float* __restrict__ pa = in  + (size_t)batch * TSC_T * TSC_ROW + unit;
    const float* __restrict__ pb = pa + TSC_UNITS;
    float*       __restrict__ po = out + (size_t)batch * TSC_T * TSC_UNITS + unit;

    float c = 0.0f;   // identity: c_0 = fma(a_0, 0, b_0) = b_0

    // 2048 steps, unroll 8 to batch independent loads (MLP ~16/thread)
    #pragma unroll 8
    for (int t = 0; t < TSC_T; ++t) {
        const float a = __ldg(pa + (size_t)t * TSC_ROW);
        const float b = __ldg(pb + (size_t)t * TSC_ROW);
        c = fmaf(a, c, b);
        po[(size_t)t * TSC_UNITS] = c;
    }
}

extern "C" void kernel_launch(void* const* d_in, const int* in_sizes, int n_in,
                              void* d_out, int out_size)
{
    const float* in = (const float*)d_in[0];
    float* out = (float*)d_out;

    const int total_threads = TSC_BATCH * TSC_UNITS;   // 32768
    const int block = 256;
    const int grid = total_threads / block;            // 128

    tempo_scan_kernel<<<grid, block>>>(in, out);
}

// round 2
// speedup vs baseline: 1.4052x; 1.4052x over previous
#include <cuda_runtime.h>

// TempoStateRNNCell: c_t = a_t * c_{t-1} + b_t along time axis (T=2048).
// inputs: (16, 2048, 4096) fp32, [:, :, :2048]=a, [:, :, 2048:]=b
// output: (16, 2048, 2048) fp32. Traffic floor = 768 MB -> HBM-bound.
//
// One thread per (batch, unit). Fully coalesced across the unit dim.
// Double-buffered register tiles (U=16) keep ~32 independent LDGs in
// flight per thread to cover DRAM latency (no reg cap this time).

#define TSC_UNITS 2048
#define TSC_T     2048
#define TSC_BATCH 16
#define TSC_ROW   (2 * TSC_UNITS)
#define U         16

__global__ void __launch_bounds__(64)
tempo_scan_kernel(const float* __restrict__ in, float* __restrict__ out)
{
    const int gid   = blockIdx.x * blockDim.x + threadIdx.x;  // 0..32767
    const int batch = gid >> 11;
    const int unit  = gid & (TSC_UNITS - 1);

    const float* __restrict__ pa = in  + (size_t)batch * TSC_T * TSC_ROW + unit;
    const float* __restrict__ pb = pa + TSC_UNITS;
    float*       __restrict__ po = out + (size_t)batch * TSC_T * TSC_UNITS + unit;

    float ca[U], cb[U], na[U], nb[U];

    // Prime tile 0
    #pragma unroll
    for (int i = 0; i < U; ++i) {
        ca[i] = __ldcs(pa + (size_t)i * TSC_ROW);
        cb[i] = __ldcs(pb + (size_t)i * TSC_ROW);
    }

    float c = 0.0f;                       // c_0 = fma(a_0, 0, b_0) = b_0
    const int NT = TSC_T / U;             // 128 tiles

    for (int tile = 0; tile < NT; ++tile) {
        const size_t base = (size_t)tile * U;

        // Prefetch next tile (independent of the serial carry chain)
        if (tile + 1 < NT) {
            const size_t nb_ = base + U;
            #pragma unroll
            for (int i = 0; i < U; ++i) {
                na[i] = __ldcs(pa + (nb_ + i) * TSC_ROW);
                nb[i] = __ldcs(pb + (nb_ + i) * TSC_ROW);
            }
        }

        // Consume current tile: serial fma chain + streaming stores
        #pragma unroll
        for (int i = 0; i < U; ++i) {
            c = fmaf(ca[i], c, cb[i]);
            __stcs(po + (base + i) * TSC_UNITS, c);
        }

        // Rotate buffers (register renames, no real moves after ptxas)
        #pragma unroll
        for (int i = 0; i < U; ++i) { ca[i] = na[i]; cb[i] = nb[i]; }
    }
}

extern "C" void kernel_launch(void* const* d_in, const int* in_sizes, int n_in,
                              void* d_out, int out_size)
{
    const float* in  = (const float*)d_in[0];
    float*       out = (float*)d_out;

    const int total_threads = TSC_BATCH * TSC_UNITS;  // 32768
    const int block = 64;
    const int grid  = total_threads / block;          // 512 blocks -> ~3.5 CTAs/SM

    tempo_scan_kernel<<<grid, block>>>(in, out);
}